// round 16
// baseline (speedup 1.0000x reference)
#include <cuda_runtime.h>
#include <cuda_bf16.h>
#include <cstdint>

#define NROWS  8192
#define HALF_N 4096
#define D      256
#define MT     128
#define NTILES 2080           // 64*65/2 upper-triangular block pairs
#define THREADS 256

// fp8 panels: 128 rows x 256 B, XOR-swizzled. A @0, B @32768.
#define SM_A  0
#define SM_B  32768
#define SMEM_TOTAL 65536

__device__ uint8_t g_zq[NROWS * D];   // normalized rows, e4m3 (2 MB, L2-resident)
__device__ float g_part[NROWS];       // per-row exp-sum (diag excluded), atomic accum
__device__ float g_pos[NROWS];        // per-row positive-pair logit

// ---------------------------------------------------------------------------
__device__ __forceinline__ uint32_t smem_u32(const void* p) {
    uint32_t a;
    asm("{ .reg .u64 t; cvta.to.shared.u64 t, %1; cvt.u32.u64 %0, t; }" : "=r"(a) : "l"(p));
    return a;
}
__device__ __forceinline__ void cp16(uint32_t dst, const void* src) {
    asm volatile("cp.async.cg.shared.global [%0], [%1], 16;" :: "r"(dst), "l"(src) : "memory");
}
#define CP_COMMIT() asm volatile("cp.async.commit_group;" ::: "memory")
#define CP_WAIT(n)  asm volatile("cp.async.wait_group %0;" :: "n"(n) : "memory")

__device__ __forceinline__ void ldsm4(uint32_t* r, uint32_t addr) {
    asm volatile("ldmatrix.sync.aligned.m8n8.x4.shared.b16 {%0,%1,%2,%3}, [%4];"
        : "=r"(r[0]), "=r"(r[1]), "=r"(r[2]), "=r"(r[3]) : "r"(addr));
}
__device__ __forceinline__ void mma_fp8(float* c, const uint32_t* a,
                                        uint32_t b0, uint32_t b1) {
    asm volatile("mma.sync.aligned.m16n8k32.row.col.f32.e4m3.e4m3.f32 "
        "{%0,%1,%2,%3}, {%4,%5,%6,%7}, {%8,%9}, {%0,%1,%2,%3};"
        : "+f"(c[0]), "+f"(c[1]), "+f"(c[2]), "+f"(c[3])
        : "r"(a[0]), "r"(a[1]), "r"(a[2]), "r"(a[3]), "r"(b0), "r"(b1));
}
__device__ __forceinline__ uint32_t pack_e4m3x4(float x, float y, float z, float w) {
    uint16_t lo, hi;
    asm("cvt.rn.satfinite.e4m3x2.f32 %0, %1, %2;" : "=h"(lo) : "f"(y), "f"(x));
    asm("cvt.rn.satfinite.e4m3x2.f32 %0, %1, %2;" : "=h"(hi) : "f"(w), "f"(z));
    return (uint32_t)lo | ((uint32_t)hi << 16);
}

// ---------------------------------------------------------------------------
// Kernel 1: L2-normalize rows -> e4m3. 4 rows/warp, 8 lanes/row:
// 8 front-batched LDG.128 per lane (MLP 8), 3-shuffle row reduction.
// Also zeroes g_part and out[0].
// ---------------------------------------------------------------------------
__global__ void __launch_bounds__(256) norm_kernel(const float* __restrict__ z1,
                                                   const float* __restrict__ z2,
                                                   float* __restrict__ out) {
    int tid = threadIdx.x;
    if (blockIdx.x < 32)                          // zero g_part (g_pos overwritten)
        g_part[blockIdx.x * 256 + tid] = 0.f;
    if (blockIdx.x == 32 && tid == 0) out[0] = 0.f;

    int wid = tid >> 5, lane = tid & 31;
    int rsub = lane >> 3;                         // row within warp's group of 4
    int sub  = lane & 7;                          // 8 lanes per row
    int row  = blockIdx.x * 32 + wid * 4 + rsub;
    const float* src = (row < HALF_N) ? z1 + (size_t)row * D
                                      : z2 + (size_t)(row - HALF_N) * D;
    const float4* s4 = (const float4*)src + sub * 8;
    float4 v[8];
    #pragma unroll
    for (int i = 0; i < 8; i++) v[i] = s4[i];     // 8 front-batched LDG.128

    float ss = 0.f;
    #pragma unroll
    for (int i = 0; i < 8; i++)
        ss += v[i].x*v[i].x + v[i].y*v[i].y + v[i].z*v[i].z + v[i].w*v[i].w;
    ss += __shfl_xor_sync(0xffffffffu, ss, 1);
    ss += __shfl_xor_sync(0xffffffffu, ss, 2);
    ss += __shfl_xor_sync(0xffffffffu, ss, 4);
    float inv = 1.0f / fmaxf(sqrtf(ss), 1e-8f);

    uint4 o0, o1;
    o0.x = pack_e4m3x4(v[0].x*inv, v[0].y*inv, v[0].z*inv, v[0].w*inv);
    o0.y = pack_e4m3x4(v[1].x*inv, v[1].y*inv, v[1].z*inv, v[1].w*inv);
    o0.z = pack_e4m3x4(v[2].x*inv, v[2].y*inv, v[2].z*inv, v[2].w*inv);
    o0.w = pack_e4m3x4(v[3].x*inv, v[3].y*inv, v[3].z*inv, v[3].w*inv);
    o1.x = pack_e4m3x4(v[4].x*inv, v[4].y*inv, v[4].z*inv, v[4].w*inv);
    o1.y = pack_e4m3x4(v[5].x*inv, v[5].y*inv, v[5].z*inv, v[5].w*inv);
    o1.z = pack_e4m3x4(v[6].x*inv, v[6].y*inv, v[6].z*inv, v[6].w*inv);
    o1.w = pack_e4m3x4(v[7].x*inv, v[7].y*inv, v[7].z*inv, v[7].w*inv);
    uint4* dst = (uint4*)(g_zq + (size_t)row * D) + sub * 2;
    dst[0] = o0;
    dst[1] = o1;
}

// ---------------------------------------------------------------------------
// Kernel 2: symmetric fp8 sim GEMM, K-split pipelined panel load.
// (Best-known config: 256 threads, warp tile m32 x n64, 2 CTAs/SM.)
// ---------------------------------------------------------------------------
__global__ void __launch_bounds__(THREADS, 2) sim_kernel() {
    __shared__ float rowsumArr[2][MT];           // sliced by cg
    __shared__ float colsumArr[4][MT];           // sliced by rgw
    extern __shared__ char smem[];
    uint32_t sb = smem_u32(smem);

    int tid = threadIdx.x, wid = tid >> 5, lane = tid & 31;
    int rgw = wid & 3;          // warp row-group: rows rgw*32 .. +31
    int cg  = wid >> 2;         // warp col-group: cols cg*64 .. +63

    // ---- map blockIdx -> (I, J), I <= J
    int t = blockIdx.x;
    int I = (int)(64.5f - sqrtf(64.5f * 64.5f - 2.0f * (float)t));
    if (I < 0) I = 0; if (I > 63) I = 63;
    while (I < 63 && (I + 1) * (128 - I) / 2 <= t) ++I;
    while (I > 0 && I * (129 - I) / 2 > t) --I;
    int J = I + (t - I * (129 - I) / 2);
    bool isDiag = (I == J), isPos = (J == I + 32);

    const char* gA = (const char*)(g_zq + (size_t)I * MT * D);
    const char* gB = (const char*)(g_zq + (size_t)J * MT * D);

    // ---- group 0: K-half 0 of both panels (chunks 0..7 per row)
    #pragma unroll
    for (int i = 0; i < 4; i++) {
        uint32_t c = i * 256 + tid, r = c >> 3, ch = c & 7;
        cp16(sb + SM_A + r * 256 + ((ch ^ (r & 7)) << 4),
             gA + (size_t)r * 256 + ch * 16);
    }
    #pragma unroll
    for (int i = 0; i < 4; i++) {
        uint32_t c = i * 256 + tid, r = c >> 3, ch = c & 7;
        cp16(sb + SM_B + r * 256 + ((ch ^ (r & 7)) << 4),
             gB + (size_t)r * 256 + ch * 16);
    }
    CP_COMMIT();
    // ---- group 1: K-half 1 (chunks 8..15)
    #pragma unroll
    for (int i = 0; i < 4; i++) {
        uint32_t c = i * 256 + tid, r = c >> 3, ch = (c & 7) + 8;
        cp16(sb + SM_A + r * 256 + ((ch ^ (r & 7)) << 4),
             gA + (size_t)r * 256 + ch * 16);
    }
    #pragma unroll
    for (int i = 0; i < 4; i++) {
        uint32_t c = i * 256 + tid, r = c >> 3, ch = (c & 7) + 8;
        cp16(sb + SM_B + r * 256 + ((ch ^ (r & 7)) << 4),
             gB + (size_t)r * 256 + ch * 16);
    }
    CP_COMMIT();

    #pragma unroll
    for (int s = 0; s < 2; s++) if (tid < MT) rowsumArr[s][tid] = 0.f;
    #pragma unroll
    for (int s = 0; s < 4; s++) if (tid < MT) colsumArr[s][tid] = 0.f;

    // ---- per-lane ldsm addressing (fp8 m16n8k32 fragment order)
    uint32_t mm = lane >> 3, rr = lane & 7;
    uint32_t rsel  = (mm & 1) * 8 + rr;
    uint32_t cbase = mm >> 1;
    uint32_t aRow0 = rgw * 32 + rsel, aRow1 = aRow0 + 16;
    uint32_t aBase0 = sb + SM_A + aRow0 * 256, aSwz0 = aRow0 & 7;
    uint32_t aBase1 = sb + SM_A + aRow1 * 256, aSwz1 = aRow1 & 7;
    uint32_t bRow[4], bSwz[4];
    #pragma unroll
    for (int q = 0; q < 4; q++) {
        uint32_t br = cg * 64 + q * 16 + rsel;
        bRow[q] = sb + SM_B + br * 256; bSwz[q] = br & 7;
    }

    float acc[2][8][4];
    #pragma unroll
    for (int rg = 0; rg < 2; rg++)
        #pragma unroll
        for (int nb = 0; nb < 8; nb++)
            #pragma unroll
            for (int e = 0; e < 4; e++) acc[rg][nb][e] = 0.f;

    // ---- K-half 0 compute (group 1 still streaming)
    CP_WAIT(1);
    __syncthreads();
    #pragma unroll
    for (int k = 0; k < 4; k++) {
        uint32_t ch = 2 * k + cbase;
        uint32_t a0[4], a1[4], b[4][4];
        ldsm4(a0, aBase0 + ((ch ^ aSwz0) << 4));
        ldsm4(a1, aBase1 + ((ch ^ aSwz1) << 4));
        #pragma unroll
        for (int q = 0; q < 4; q++)
            ldsm4(b[q], bRow[q] + ((ch ^ bSwz[q]) << 4));
        #pragma unroll
        for (int q = 0; q < 4; q++) {
            mma_fp8(acc[0][2*q],   a0, b[q][0], b[q][2]);
            mma_fp8(acc[0][2*q+1], a0, b[q][1], b[q][3]);
            mma_fp8(acc[1][2*q],   a1, b[q][0], b[q][2]);
            mma_fp8(acc[1][2*q+1], a1, b[q][1], b[q][3]);
        }
    }
    // ---- K-half 1 compute
    CP_WAIT(0);
    __syncthreads();
    #pragma unroll
    for (int k = 4; k < 8; k++) {
        uint32_t ch = 2 * k + cbase;
        uint32_t a0[4], a1[4], b[4][4];
        ldsm4(a0, aBase0 + ((ch ^ aSwz0) << 4));
        ldsm4(a1, aBase1 + ((ch ^ aSwz1) << 4));
        #pragma unroll
        for (int q = 0; q < 4; q++)
            ldsm4(b[q], bRow[q] + ((ch ^ bSwz[q]) << 4));
        #pragma unroll
        for (int q = 0; q < 4; q++) {
            mma_fp8(acc[0][2*q],   a0, b[q][0], b[q][2]);
            mma_fp8(acc[0][2*q+1], a0, b[q][1], b[q][3]);
            mma_fp8(acc[1][2*q],   a1, b[q][0], b[q][2]);
            mma_fp8(acc[1][2*q+1], a1, b[q][1], b[q][3]);
        }
    }

    // ---- epilogue: exp(2a) = exp2(a * 2/ln2)
    const float C2 = 2.8853901817779268f;
    int ilBase = rgw * 32 + (lane >> 2);
    int jlBase = cg * 64 + ((lane & 3) << 1);
    float rsum[2][2] = {{0.f,0.f},{0.f,0.f}};
    float colacc[8][2];
    #pragma unroll
    for (int nb = 0; nb < 8; nb++) { colacc[nb][0] = 0.f; colacc[nb][1] = 0.f; }

    if (!isDiag && !isPos) {
        #pragma unroll
        for (int rg = 0; rg < 2; rg++)
            #pragma unroll
            for (int nb = 0; nb < 8; nb++)
                #pragma unroll
                for (int e = 0; e < 4; e++) {
                    float v = exp2f(C2 * acc[rg][nb][e]);
                    rsum[rg][e >> 1] += v;
                    colacc[nb][e & 1] += v;
                }
    } else {
        #pragma unroll
        for (int rg = 0; rg < 2; rg++)
            #pragma unroll
            for (int e = 0; e < 4; e++) {
                int il = ilBase + rg * 16 + 8 * (e >> 1);
                #pragma unroll
                for (int nb = 0; nb < 8; nb++) {
                    int jl = jlBase + nb * 8 + (e & 1);
                    float v = exp2f(C2 * acc[rg][nb][e]);
                    if (isDiag && jl == il) v = 0.f;        // exact self-skip
                    if (isPos && jl == il) {                // positive pair
                        float sim = 2.f * acc[rg][nb][e];
                        int gi = I * MT + il;
                        g_pos[gi] = sim; g_pos[gi + HALF_N] = sim;
                    }
                    rsum[rg][e >> 1] += v;
                    colacc[nb][e & 1] += v;
                }
            }
    }

    // row reduction: 4 lanes share a row; write to cg-slice (no atomics)
    #pragma unroll
    for (int rg = 0; rg < 2; rg++)
        #pragma unroll
        for (int h = 0; h < 2; h++) {
            float v = rsum[rg][h];
            v += __shfl_xor_sync(0xffffffffu, v, 1);
            v += __shfl_xor_sync(0xffffffffu, v, 2);
            if ((lane & 3) == 0)
                rowsumArr[cg][ilBase + rg * 16 + 8 * h] = v;
        }
    // column reduction: sum the 8 row-lanes; write to rgw-slice (no atomics)
    #pragma unroll
    for (int nb = 0; nb < 8; nb++)
        #pragma unroll
        for (int p = 0; p < 2; p++) {
            float v = colacc[nb][p];
            v += __shfl_xor_sync(0xffffffffu, v, 4);
            v += __shfl_xor_sync(0xffffffffu, v, 8);
            v += __shfl_xor_sync(0xffffffffu, v, 16);
            if (lane < 4)
                colsumArr[rgw][jlBase + nb * 8 + p] = v;
        }
    __syncthreads();

    if (tid < MT) {
        atomicAdd(&g_part[I * MT + tid], rowsumArr[0][tid] + rowsumArr[1][tid]);
    } else if (!isDiag) {
        int r = tid - MT;
        atomicAdd(&g_part[J * MT + r],
                  (colsumArr[0][r] + colsumArr[1][r]) +
                  (colsumArr[2][r] + colsumArr[3][r]));
    }
}

// ---------------------------------------------------------------------------
// Kernel 3: multi-block per-row loss + atomic mean (out pre-zeroed by norm).
// ---------------------------------------------------------------------------
__global__ void __launch_bounds__(256) reduce_kernel(float* __restrict__ out) {
    __shared__ float red[8];
    int t = threadIdx.x, w = t >> 5, lane = t & 31;
    int r = blockIdx.x * 256 + t;
    float v = __logf(g_part[r]) - g_pos[r];
    #pragma unroll
    for (int o = 16; o > 0; o >>= 1) v += __shfl_xor_sync(0xffffffffu, v, o);
    if (lane == 0) red[w] = v;
    __syncthreads();
    if (t < 8) {
        float s = red[t];
        s += __shfl_xor_sync(0xffu, s, 1);
        s += __shfl_xor_sync(0xffu, s, 2);
        s += __shfl_xor_sync(0xffu, s, 4);
        if (t == 0) atomicAdd(out, s * (1.0f / (float)NROWS));
    }
}

// ---------------------------------------------------------------------------
extern "C" void kernel_launch(void* const* d_in, const int* in_sizes, int n_in,
                              void* d_out, int out_size) {
    const float* z1 = (const float*)d_in[0];
    const float* z2 = (const float*)d_in[1];
    float* out = (float*)d_out;

    cudaFuncSetAttribute(sim_kernel,
                         cudaFuncAttributeMaxDynamicSharedMemorySize, SMEM_TOTAL);

    norm_kernel<<<NROWS / 32, 256>>>(z1, z2, out);
    sim_kernel<<<NTILES, THREADS, SMEM_TOTAL>>>();
    reduce_kernel<<<NROWS / 256, 256>>>(out);
}

// round 17
// speedup vs baseline: 1.0444x; 1.0444x over previous
#include <cuda_runtime.h>
#include <cuda_bf16.h>
#include <cstdint>

#define NROWS  8192
#define HALF_N 4096
#define D      256
#define MT     128
#define NTILES 2080           // 64*65/2 upper-triangular block pairs
#define THREADS 256

// fp8 panels: 128 rows x 256 B, XOR-swizzled. A @0, B @32768.
#define SM_A  0
#define SM_B  32768
#define SMEM_TOTAL 65536

__device__ uint8_t g_zq[NROWS * D];   // normalized rows, e4m3 (2 MB, L2-resident)
__device__ float g_part[NROWS];       // per-row exp-sum (diag excluded), atomic accum
__device__ float g_pos[NROWS];        // per-row positive-pair logit

// ---------------------------------------------------------------------------
__device__ __forceinline__ uint32_t smem_u32(const void* p) {
    uint32_t a;
    asm("{ .reg .u64 t; cvta.to.shared.u64 t, %1; cvt.u32.u64 %0, t; }" : "=r"(a) : "l"(p));
    return a;
}
__device__ __forceinline__ void cp16(uint32_t dst, const void* src) {
    asm volatile("cp.async.cg.shared.global [%0], [%1], 16;" :: "r"(dst), "l"(src) : "memory");
}
#define CP_COMMIT() asm volatile("cp.async.commit_group;" ::: "memory")
#define CP_WAIT(n)  asm volatile("cp.async.wait_group %0;" :: "n"(n) : "memory")

__device__ __forceinline__ void ldsm4(uint32_t* r, uint32_t addr) {
    asm volatile("ldmatrix.sync.aligned.m8n8.x4.shared.b16 {%0,%1,%2,%3}, [%4];"
        : "=r"(r[0]), "=r"(r[1]), "=r"(r[2]), "=r"(r[3]) : "r"(addr));
}
__device__ __forceinline__ void mma_fp8(float* c, const uint32_t* a,
                                        uint32_t b0, uint32_t b1) {
    asm volatile("mma.sync.aligned.m16n8k32.row.col.f32.e4m3.e4m3.f32 "
        "{%0,%1,%2,%3}, {%4,%5,%6,%7}, {%8,%9}, {%0,%1,%2,%3};"
        : "+f"(c[0]), "+f"(c[1]), "+f"(c[2]), "+f"(c[3])
        : "r"(a[0]), "r"(a[1]), "r"(a[2]), "r"(a[3]), "r"(b0), "r"(b1));
}
__device__ __forceinline__ uint32_t pack_e4m3x4(float x, float y, float z, float w) {
    uint16_t lo, hi;
    asm("cvt.rn.satfinite.e4m3x2.f32 %0, %1, %2;" : "=h"(lo) : "f"(y), "f"(x));
    asm("cvt.rn.satfinite.e4m3x2.f32 %0, %1, %2;" : "=h"(hi) : "f"(w), "f"(z));
    return (uint32_t)lo | ((uint32_t)hi << 16);
}

// ---------------------------------------------------------------------------
// Kernel 1: L2-normalize rows -> e4m3 (2 rows per warp, best measured shape);
// zeroes g_part and out[0].
// ---------------------------------------------------------------------------
__global__ void __launch_bounds__(256) norm_kernel(const float* __restrict__ z1,
                                                   const float* __restrict__ z2,
                                                   float* __restrict__ out) {
    int tid = threadIdx.x;
    if (blockIdx.x < 32)                          // zero g_part (g_pos overwritten)
        g_part[blockIdx.x * 256 + tid] = 0.f;
    if (blockIdx.x == 32 && tid == 0) out[0] = 0.f;
    int wid = tid >> 5, lid = tid & 31;
    int row0 = blockIdx.x * 16 + wid * 2;
    int row1 = row0 + 1;
    const float* p0 = (row0 < HALF_N) ? z1 + (size_t)row0 * D
                                      : z2 + (size_t)(row0 - HALF_N) * D;
    const float* p1 = (row1 < HALF_N) ? z1 + (size_t)row1 * D
                                      : z2 + (size_t)(row1 - HALF_N) * D;
    const float4* s0 = (const float4*)p0;
    const float4* s1 = (const float4*)p1;
    float4 a0 = s0[lid], b0 = s0[lid + 32];
    float4 a1 = s1[lid], b1 = s1[lid + 32];
    float ss0 = a0.x*a0.x + a0.y*a0.y + a0.z*a0.z + a0.w*a0.w
              + b0.x*b0.x + b0.y*b0.y + b0.z*b0.z + b0.w*b0.w;
    float ss1 = a1.x*a1.x + a1.y*a1.y + a1.z*a1.z + a1.w*a1.w
              + b1.x*b1.x + b1.y*b1.y + b1.z*b1.z + b1.w*b1.w;
    #pragma unroll
    for (int o = 16; o > 0; o >>= 1) {
        ss0 += __shfl_xor_sync(0xffffffffu, ss0, o);
        ss1 += __shfl_xor_sync(0xffffffffu, ss1, o);
    }
    float inv0 = 1.0f / fmaxf(sqrtf(ss0), 1e-8f);
    float inv1 = 1.0f / fmaxf(sqrtf(ss1), 1e-8f);
    uint32_t* d0 = (uint32_t*)(g_zq + (size_t)row0 * D);
    uint32_t* d1 = (uint32_t*)(g_zq + (size_t)row1 * D);
    d0[lid]      = pack_e4m3x4(a0.x*inv0, a0.y*inv0, a0.z*inv0, a0.w*inv0);
    d0[lid + 32] = pack_e4m3x4(b0.x*inv0, b0.y*inv0, b0.z*inv0, b0.w*inv0);
    d1[lid]      = pack_e4m3x4(a1.x*inv1, a1.y*inv1, a1.z*inv1, a1.w*inv1);
    d1[lid + 32] = pack_e4m3x4(b1.x*inv1, b1.y*inv1, b1.z*inv1, b1.w*inv1);
}

// ---------------------------------------------------------------------------
// Kernel 2: symmetric fp8 sim GEMM, K-split pipelined panel load.
// (Champion config: 256 threads, warp tile m32 x n64, 2 CTAs/SM.)
// ---------------------------------------------------------------------------
__global__ void __launch_bounds__(THREADS, 2) sim_kernel() {
    __shared__ float rowsumArr[2][MT];           // sliced by cg
    __shared__ float colsumArr[4][MT];           // sliced by rgw
    extern __shared__ char smem[];
    uint32_t sb = smem_u32(smem);

    int tid = threadIdx.x, wid = tid >> 5, lane = tid & 31;
    int rgw = wid & 3;          // warp row-group: rows rgw*32 .. +31
    int cg  = wid >> 2;         // warp col-group: cols cg*64 .. +63

    // ---- map blockIdx -> (I, J), I <= J
    int t = blockIdx.x;
    int I = (int)(64.5f - sqrtf(64.5f * 64.5f - 2.0f * (float)t));
    if (I < 0) I = 0; if (I > 63) I = 63;
    while (I < 63 && (I + 1) * (128 - I) / 2 <= t) ++I;
    while (I > 0 && I * (129 - I) / 2 > t) --I;
    int J = I + (t - I * (129 - I) / 2);
    bool isDiag = (I == J), isPos = (J == I + 32);

    const char* gA = (const char*)(g_zq + (size_t)I * MT * D);
    const char* gB = (const char*)(g_zq + (size_t)J * MT * D);

    // ---- group 0: K-half 0 of both panels (chunks 0..7 per row)
    #pragma unroll
    for (int i = 0; i < 4; i++) {
        uint32_t c = i * 256 + tid, r = c >> 3, ch = c & 7;
        cp16(sb + SM_A + r * 256 + ((ch ^ (r & 7)) << 4),
             gA + (size_t)r * 256 + ch * 16);
    }
    #pragma unroll
    for (int i = 0; i < 4; i++) {
        uint32_t c = i * 256 + tid, r = c >> 3, ch = c & 7;
        cp16(sb + SM_B + r * 256 + ((ch ^ (r & 7)) << 4),
             gB + (size_t)r * 256 + ch * 16);
    }
    CP_COMMIT();
    // ---- group 1: K-half 1 (chunks 8..15)
    #pragma unroll
    for (int i = 0; i < 4; i++) {
        uint32_t c = i * 256 + tid, r = c >> 3, ch = (c & 7) + 8;
        cp16(sb + SM_A + r * 256 + ((ch ^ (r & 7)) << 4),
             gA + (size_t)r * 256 + ch * 16);
    }
    #pragma unroll
    for (int i = 0; i < 4; i++) {
        uint32_t c = i * 256 + tid, r = c >> 3, ch = (c & 7) + 8;
        cp16(sb + SM_B + r * 256 + ((ch ^ (r & 7)) << 4),
             gB + (size_t)r * 256 + ch * 16);
    }
    CP_COMMIT();

    #pragma unroll
    for (int s = 0; s < 2; s++) if (tid < MT) rowsumArr[s][tid] = 0.f;
    #pragma unroll
    for (int s = 0; s < 4; s++) if (tid < MT) colsumArr[s][tid] = 0.f;

    // ---- per-lane ldsm addressing (fp8 m16n8k32 fragment order)
    uint32_t mm = lane >> 3, rr = lane & 7;
    uint32_t rsel  = (mm & 1) * 8 + rr;
    uint32_t cbase = mm >> 1;
    uint32_t aRow0 = rgw * 32 + rsel, aRow1 = aRow0 + 16;
    uint32_t aBase0 = sb + SM_A + aRow0 * 256, aSwz0 = aRow0 & 7;
    uint32_t aBase1 = sb + SM_A + aRow1 * 256, aSwz1 = aRow1 & 7;
    uint32_t bRow[4], bSwz[4];
    #pragma unroll
    for (int q = 0; q < 4; q++) {
        uint32_t br = cg * 64 + q * 16 + rsel;
        bRow[q] = sb + SM_B + br * 256; bSwz[q] = br & 7;
    }

    float acc[2][8][4];
    #pragma unroll
    for (int rg = 0; rg < 2; rg++)
        #pragma unroll
        for (int nb = 0; nb < 8; nb++)
            #pragma unroll
            for (int e = 0; e < 4; e++) acc[rg][nb][e] = 0.f;

    // ---- K-half 0 compute (group 1 still streaming)
    CP_WAIT(1);
    __syncthreads();
    #pragma unroll
    for (int k = 0; k < 4; k++) {
        uint32_t ch = 2 * k + cbase;
        uint32_t a0[4], a1[4], b[4][4];
        ldsm4(a0, aBase0 + ((ch ^ aSwz0) << 4));
        ldsm4(a1, aBase1 + ((ch ^ aSwz1) << 4));
        #pragma unroll
        for (int q = 0; q < 4; q++)
            ldsm4(b[q], bRow[q] + ((ch ^ bSwz[q]) << 4));
        #pragma unroll
        for (int q = 0; q < 4; q++) {
            mma_fp8(acc[0][2*q],   a0, b[q][0], b[q][2]);
            mma_fp8(acc[0][2*q+1], a0, b[q][1], b[q][3]);
            mma_fp8(acc[1][2*q],   a1, b[q][0], b[q][2]);
            mma_fp8(acc[1][2*q+1], a1, b[q][1], b[q][3]);
        }
    }
    // ---- K-half 1 compute
    CP_WAIT(0);
    __syncthreads();
    #pragma unroll
    for (int k = 4; k < 8; k++) {
        uint32_t ch = 2 * k + cbase;
        uint32_t a0[4], a1[4], b[4][4];
        ldsm4(a0, aBase0 + ((ch ^ aSwz0) << 4));
        ldsm4(a1, aBase1 + ((ch ^ aSwz1) << 4));
        #pragma unroll
        for (int q = 0; q < 4; q++)
            ldsm4(b[q], bRow[q] + ((ch ^ bSwz[q]) << 4));
        #pragma unroll
        for (int q = 0; q < 4; q++) {
            mma_fp8(acc[0][2*q],   a0, b[q][0], b[q][2]);
            mma_fp8(acc[0][2*q+1], a0, b[q][1], b[q][3]);
            mma_fp8(acc[1][2*q],   a1, b[q][0], b[q][2]);
            mma_fp8(acc[1][2*q+1], a1, b[q][1], b[q][3]);
        }
    }

    // ---- epilogue: exp(2a) = exp2(a * 2/ln2)
    const float C2 = 2.8853901817779268f;
    int ilBase = rgw * 32 + (lane >> 2);
    int jlBase = cg * 64 + ((lane & 3) << 1);
    float rsum[2][2] = {{0.f,0.f},{0.f,0.f}};
    float colacc[8][2];
    #pragma unroll
    for (int nb = 0; nb < 8; nb++) { colacc[nb][0] = 0.f; colacc[nb][1] = 0.f; }

    if (!isDiag && !isPos) {
        #pragma unroll
        for (int rg = 0; rg < 2; rg++)
            #pragma unroll
            for (int nb = 0; nb < 8; nb++)
                #pragma unroll
                for (int e = 0; e < 4; e++) {
                    float v = exp2f(C2 * acc[rg][nb][e]);
                    rsum[rg][e >> 1] += v;
                    colacc[nb][e & 1] += v;
                }
    } else {
        #pragma unroll
        for (int rg = 0; rg < 2; rg++)
            #pragma unroll
            for (int e = 0; e < 4; e++) {
                int il = ilBase + rg * 16 + 8 * (e >> 1);
                #pragma unroll
                for (int nb = 0; nb < 8; nb++) {
                    int jl = jlBase + nb * 8 + (e & 1);
                    float v = exp2f(C2 * acc[rg][nb][e]);
                    if (isDiag && jl == il) v = 0.f;        // exact self-skip
                    if (isPos && jl == il) {                // positive pair
                        float sim = 2.f * acc[rg][nb][e];
                        int gi = I * MT + il;
                        g_pos[gi] = sim; g_pos[gi + HALF_N] = sim;
                    }
                    rsum[rg][e >> 1] += v;
                    colacc[nb][e & 1] += v;
                }
            }
    }

    // row reduction: 4 lanes share a row; write to cg-slice (no atomics)
    #pragma unroll
    for (int rg = 0; rg < 2; rg++)
        #pragma unroll
        for (int h = 0; h < 2; h++) {
            float v = rsum[rg][h];
            v += __shfl_xor_sync(0xffffffffu, v, 1);
            v += __shfl_xor_sync(0xffffffffu, v, 2);
            if ((lane & 3) == 0)
                rowsumArr[cg][ilBase + rg * 16 + 8 * h] = v;
        }
    // column reduction: sum the 8 row-lanes; write to rgw-slice (no atomics)
    #pragma unroll
    for (int nb = 0; nb < 8; nb++)
        #pragma unroll
        for (int p = 0; p < 2; p++) {
            float v = colacc[nb][p];
            v += __shfl_xor_sync(0xffffffffu, v, 4);
            v += __shfl_xor_sync(0xffffffffu, v, 8);
            v += __shfl_xor_sync(0xffffffffu, v, 16);
            if (lane < 4)
                colsumArr[rgw][jlBase + nb * 8 + p] = v;
        }
    __syncthreads();

    if (tid < MT) {
        atomicAdd(&g_part[I * MT + tid], rowsumArr[0][tid] + rowsumArr[1][tid]);
    } else if (!isDiag) {
        int r = tid - MT;
        atomicAdd(&g_part[J * MT + r],
                  (colsumArr[0][r] + colsumArr[1][r]) +
                  (colsumArr[2][r] + colsumArr[3][r]));
    }
}

// ---------------------------------------------------------------------------
// Kernel 3: per-row loss + warp-shuffle block sum + atomic mean.
// ---------------------------------------------------------------------------
__global__ void __launch_bounds__(256) reduce_kernel(float* __restrict__ out) {
    __shared__ float red[8];
    int t = threadIdx.x, w = t >> 5, lane = t & 31;
    int r = blockIdx.x * 256 + t;
    float v = __logf(g_part[r]) - g_pos[r];
    #pragma unroll
    for (int o = 16; o > 0; o >>= 1) v += __shfl_xor_sync(0xffffffffu, v, o);
    if (lane == 0) red[w] = v;
    __syncthreads();
    if (t < 8) {
        float s = red[t];
        s += __shfl_xor_sync(0xffu, s, 1);
        s += __shfl_xor_sync(0xffu, s, 2);
        s += __shfl_xor_sync(0xffu, s, 4);
        if (t == 0) atomicAdd(out, s * (1.0f / (float)NROWS));
    }
}

// ---------------------------------------------------------------------------
extern "C" void kernel_launch(void* const* d_in, const int* in_sizes, int n_in,
                              void* d_out, int out_size) {
    const float* z1 = (const float*)d_in[0];
    const float* z2 = (const float*)d_in[1];
    float* out = (float*)d_out;

    cudaFuncSetAttribute(sim_kernel,
                         cudaFuncAttributeMaxDynamicSharedMemorySize, SMEM_TOTAL);

    norm_kernel<<<NROWS / 16, 256>>>(z1, z2, out);
    sim_kernel<<<NTILES, THREADS, SMEM_TOTAL>>>();
    reduce_kernel<<<NROWS / 256, 256>>>(out);
}